// round 11
// baseline (speedup 1.0000x reference)
#include <cuda_runtime.h>
#include <cuda_bf16.h>
#include <cstdint>

// GINNet on GB300. R10: fp16 gather REVERTED (R9 bought ~0 and cost 27x
// accuracy margin -> agg is latency-bound, not BW-bound). Edge loop unrolled
// x4 for MLP; setup kernels merged; counts folded into gsum.
// R8 mma.sync bf16-split GEMM + fused BN prologues intact.

#define NN 100000
#define NE 1600000
#define DD 128
#define NG 64

#define SCAN_CHUNK 1024
#define SCAN_NB ((NN + SCAN_CHUNK - 1) / SCAN_CHUNK)   // 98

#define GM_GRID ((NN + 127) / 128)                      // 782
#define GM_SMEM 131072

// ---------------- device scratch (allocation-free contract) ----------------
__device__ __align__(128) float g_z[NN * DD];   // aggregated features
__device__ __align__(128) float g_y[NN * DD];   // GEMM1 output (pre-BN1)
__device__ __align__(128) float g_h[NN * DD];   // GEMM2 output (pre-BN2)
__device__ __align__(128) unsigned char g_wblk[6][65536]; // W^T bf16 hi|lo, swizzled
__device__ int   g_cnt[NN];
__device__ int   g_ptr[NN + 1];
__device__ int   g_cur[NN];
__device__ int   g_srcs[NE];
__device__ int   g_bsum[SCAN_NB];
__device__ int   g_boff[SCAN_NB];
__device__ float g_ssum[6][DD];
__device__ float g_ssq[6][DD];
__device__ float g_gsum[NG * DD];
__device__ int   g_gcnt[NG];
__device__ int   g_flags[2];                    // [0]=edge idx is64, [1]=batch is64

// ---------------- PTX helpers ----------------
__device__ __forceinline__ uint32_t smem_u32(const void* p) {
    uint32_t a;
    asm("{ .reg .u64 t; cvta.to.shared.u64 t, %1; cvt.u32.u64 %0, t; }"
        : "=r"(a) : "l"(p));
    return a;
}
__device__ __forceinline__ void ldsm4(uint32_t* r, uint32_t addr) {
    asm volatile("ldmatrix.sync.aligned.m8n8.x4.shared.b16 {%0,%1,%2,%3}, [%4];"
                 : "=r"(r[0]), "=r"(r[1]), "=r"(r[2]), "=r"(r[3]) : "r"(addr));
}
__device__ __forceinline__ void mma16816(float* d, const uint32_t* a,
                                         const uint32_t* b) {
    asm volatile(
        "mma.sync.aligned.m16n8k16.row.col.f32.bf16.bf16.f32 "
        "{%0,%1,%2,%3}, {%4,%5,%6,%7}, {%8,%9}, {%0,%1,%2,%3};"
        : "+f"(d[0]), "+f"(d[1]), "+f"(d[2]), "+f"(d[3])
        : "r"(a[0]), "r"(a[1]), "r"(a[2]), "r"(a[3]), "r"(b[0]), "r"(b[1]));
}
__device__ __forceinline__ uint32_t pack_bf16x2(float lo, float hi) {
    __nv_bfloat16 l = __float2bfloat16(lo), h = __float2bfloat16(hi);
    return (uint32_t)__bfloat16_as_ushort(l) |
           ((uint32_t)__bfloat16_as_ushort(h) << 16);
}

// ---------------- misc helpers ----------------
__device__ __forceinline__ int get_idx(const void* p, long long i, int is64) {
    if (is64) return (int)((const long long*)p)[i];
    return ((const int*)p)[i];
}

__device__ __forceinline__ void bn_affine_block(int slot, const float* gm,
                                                const float* bt, float* sA,
                                                float* sC, int tid) {
    if (slot >= 0 && tid < DD) {
        float mean = g_ssum[slot][tid] * (1.f / NN);
        float var = g_ssq[slot][tid] * (1.f / NN) - mean * mean;
        float a = gm[tid] * rsqrtf(var + 1e-5f);
        sA[tid] = a;
        sC[tid] = bt[tid] - mean * a;
    }
}

__device__ __forceinline__ float4 act4(float4 v, float4 a, float4 c) {
    v.x = fmaxf(fmaf(v.x, a.x, c.x), 0.f);
    v.y = fmaxf(fmaf(v.y, a.y, c.y), 0.f);
    v.z = fmaxf(fmaf(v.z, a.z, c.z), 0.f);
    v.w = fmaxf(fmaf(v.w, a.w, c.w), 0.f);
    return v;
}

// ---------------- merged setup: zero + detect + wprep ----------------
__global__ void k_setup(const void* ei, const void* bt,
                        const float* __restrict__ W1,
                        const float* __restrict__ W2) {
    int i = blockIdx.x * blockDim.x + threadIdx.x;
    if (i < NN) g_cnt[i] = 0;
    if (i < 6 * DD) { ((float*)g_ssum)[i] = 0.f; ((float*)g_ssq)[i] = 0.f; }
    if (i < NG * DD) g_gsum[i] = 0.f;
    if (i < NG) g_gcnt[i] = 0;
    // W^T split to bf16 hi/lo, [n][k] 256B rows with xor-(n&7)<<4 swizzle
    if (i < 6 * DD * DD) {
        int m = i >> 14;
        int r = i & 16383;
        int n = r >> 7, k = r & 127;
        int l = m >> 1;
        const float* W = (m & 1) ? (W2 + l * DD * DD) : (W1 + l * DD * DD);
        float v = W[k * DD + n];
        __nv_bfloat16 h = __float2bfloat16(v);
        __nv_bfloat16 lo = __float2bfloat16(v - __bfloat162float(h));
        int off = n * 256 + k * 2;
        int sw = off ^ ((n & 7) << 4);
        *(__nv_bfloat16*)(g_wblk[m] + sw) = h;
        *(__nv_bfloat16*)(g_wblk[m] + 32768 + sw) = lo;
    }
    if (blockIdx.x == 0) {
        __shared__ int bad[2];
        if (threadIdx.x < 2) bad[threadIdx.x] = 0;
        __syncthreads();
        const long long* pe = (const long long*)ei;
        const long long* pb = (const long long*)bt;
        for (int j = threadIdx.x; j < 4096; j += blockDim.x) {
            long long v = pe[(long long)j * 390];
            if (v < 0 || v >= NN) atomicOr(&bad[0], 1);
            long long w = pb[(long long)j * 12];
            if (w < 0 || w >= NG) atomicOr(&bad[1], 1);
        }
        __syncthreads();
        if (threadIdx.x == 0) {
            g_flags[0] = bad[0] ? 0 : 1;
            g_flags[1] = bad[1] ? 0 : 1;
        }
    }
}

__global__ void k_count(const void* ei) {
    int e = blockIdx.x * blockDim.x + threadIdx.x;
    if (e >= NE) return;
    int t = get_idx(ei, (long long)NE + e, g_flags[0]);
    atomicAdd(&g_cnt[t], 1);
}

__global__ void k_scanA() {
    __shared__ int wsum[8];
    int b = blockIdx.x, tid = threadIdx.x;
    int base = b * SCAN_CHUNK + tid * 4;
    int s = 0;
#pragma unroll
    for (int j = 0; j < 4; j++) { int i = base + j; if (i < NN) s += g_cnt[i]; }
#pragma unroll
    for (int o = 16; o > 0; o >>= 1) s += __shfl_xor_sync(0xffffffffu, s, o);
    if ((tid & 31) == 0) wsum[tid >> 5] = s;
    __syncthreads();
    if (tid == 0) {
        int t = 0;
#pragma unroll
        for (int w = 0; w < 8; w++) t += wsum[w];
        g_bsum[b] = t;
    }
}

__global__ void k_scanB() {
    __shared__ int sh[128];
    int t = threadIdx.x;
    sh[t] = (t < SCAN_NB) ? g_bsum[t] : 0;
    __syncthreads();
#pragma unroll
    for (int off = 1; off < 128; off <<= 1) {
        int v = (t >= off) ? sh[t - off] : 0;
        __syncthreads();
        sh[t] += v;
        __syncthreads();
    }
    if (t < SCAN_NB) g_boff[t] = (t == 0) ? 0 : sh[t - 1];
}

__global__ void k_scanC() {
    __shared__ int wexc[8];
    int b = blockIdx.x, tid = threadIdx.x;
    int lane = tid & 31, wid = tid >> 5;
    int base = b * SCAN_CHUNK + tid * 4;
    int c[4];
    int tsum = 0;
#pragma unroll
    for (int j = 0; j < 4; j++) {
        int i = base + j;
        c[j] = (i < NN) ? g_cnt[i] : 0;
        tsum += c[j];
    }
    int incl = tsum;
#pragma unroll
    for (int o = 1; o < 32; o <<= 1) {
        int v = __shfl_up_sync(0xffffffffu, incl, o);
        if (lane >= o) incl += v;
    }
    if (lane == 31) wexc[wid] = incl;
    __syncthreads();
    if (tid == 0) {
        int run = 0;
#pragma unroll
        for (int w = 0; w < 8; w++) { int v = wexc[w]; wexc[w] = run; run += v; }
    }
    __syncthreads();
    int p = g_boff[b] + wexc[wid] + (incl - tsum);
#pragma unroll
    for (int j = 0; j < 4; j++) {
        int i = base + j;
        if (i < NN) {
            g_ptr[i] = p; g_cur[i] = p; p += c[j];
            if (i == NN - 1) g_ptr[NN] = p;
        }
    }
}

__global__ void k_fill(const void* ei) {
    int e = blockIdx.x * blockDim.x + threadIdx.x;
    if (e >= NE) return;
    int is64 = g_flags[0];
    int s = get_idx(ei, e, is64);
    int t = get_idx(ei, (long long)NE + e, is64);
    int pos = atomicAdd(&g_cur[t], 1);
    g_srcs[pos] = s;
}

// ---------------- aggregation: warp per node, x4-unrolled edge loop --------
__global__ void k_agg(const float* __restrict__ x, int useX, int slot,
                      const float* __restrict__ gm, const float* __restrict__ bt,
                      const float* __restrict__ epsArr, int layer) {
    __shared__ __align__(16) float sAf[DD], sCf[DD];
    int tid = threadIdx.x;
    bn_affine_block(slot, gm, bt, sAf, sCf, tid);
    __syncthreads();

    int gt = blockIdx.x * blockDim.x + tid;
    int node = gt >> 5;
    int lane = gt & 31;
    if (node >= NN) return;
    const float4* hin = useX ? (const float4*)x : (const float4*)g_h;
    float4 ca = make_float4(1.f, 1.f, 1.f, 1.f);
    float4 cc = make_float4(0.f, 0.f, 0.f, 0.f);
    if (slot >= 0) {
        ca = ((const float4*)sAf)[lane];
        cc = ((const float4*)sCf)[lane];
    }
    float epsl = 1.f + epsArr[layer];
    int beg = g_ptr[node], end = g_ptr[node + 1];
    float4 v = hin[node * 32 + lane];
    if (slot >= 0) v = act4(v, ca, cc);
    float4 acc = make_float4(v.x * epsl, v.y * epsl, v.z * epsl, v.w * epsl);

    int e = beg;
    for (; e + 4 <= end; e += 4) {
        int s0 = __ldg(&g_srcs[e]);
        int s1 = __ldg(&g_srcs[e + 1]);
        int s2 = __ldg(&g_srcs[e + 2]);
        int s3 = __ldg(&g_srcs[e + 3]);
        float4 u0 = hin[s0 * 32 + lane];
        float4 u1 = hin[s1 * 32 + lane];
        float4 u2 = hin[s2 * 32 + lane];
        float4 u3 = hin[s3 * 32 + lane];
        if (slot >= 0) {
            u0 = act4(u0, ca, cc); u1 = act4(u1, ca, cc);
            u2 = act4(u2, ca, cc); u3 = act4(u3, ca, cc);
        }
        acc.x += (u0.x + u1.x) + (u2.x + u3.x);
        acc.y += (u0.y + u1.y) + (u2.y + u3.y);
        acc.z += (u0.z + u1.z) + (u2.z + u3.z);
        acc.w += (u0.w + u1.w) + (u2.w + u3.w);
    }
    for (; e < end; e++) {
        int s = __ldg(&g_srcs[e]);
        float4 u = hin[s * 32 + lane];
        if (slot >= 0) u = act4(u, ca, cc);
        acc.x += u.x; acc.y += u.y; acc.z += u.z; acc.w += u.w;
    }
    ((float4*)g_z)[node * 32 + lane] = acc;
}

// ---------------- mma.sync GEMM: Y[128x128 tile] = act(A) @ W ---------------
__global__ __launch_bounds__(256, 1)
void k_gemmM(int srcSel, int dstSel, const float* __restrict__ gm,
             const float* __restrict__ bt, int actSlot, int statSlot, int wsel) {
    extern __shared__ unsigned char dyn[];
    __shared__ float cs[DD], cq[DD];
    __shared__ __align__(16) float sAf[DD], sCf[DD];
    unsigned char* Ahi = dyn;
    unsigned char* Alo = dyn + 32768;
    unsigned char* Bhi = dyn + 65536;

    int tid = threadIdx.x;
    int wid = tid >> 5, lane = tid & 31;
    int mBase = blockIdx.x * 128;
    const float* A = srcSel ? g_y : g_z;
    float* Y = dstSel ? g_h : g_y;

    if (tid < DD) { cs[tid] = 0.f; cq[tid] = 0.f; }
    bn_affine_block(actSlot, gm, bt, sAf, sCf, tid);

    // stage B: 64KB coalesced copy (hi|lo pre-swizzled, contiguous)
    {
        const float4* src = (const float4*)g_wblk[wsel];
        float4* dst = (float4*)Bhi;
#pragma unroll
        for (int i = 0; i < 16; i++) dst[tid + i * 256] = src[tid + i * 256];
    }
    __syncthreads();

    // stage A: 2 threads per row, 64 cols each; act + split + swizzled store
    {
        int r = tid >> 1, ch = tid & 1;
        int grow = mBase + r;
        bool valid = grow < NN;
        const float4* A4 = (const float4*)A;
#pragma unroll
        for (int c = 0; c < 8; c++) {
            int f4i = ch * 16 + c * 2;
            float4 v0 = make_float4(0.f, 0.f, 0.f, 0.f);
            float4 v1 = v0;
            if (valid) {
                v0 = A4[grow * 32 + f4i];
                v1 = A4[grow * 32 + f4i + 1];
            }
            if (actSlot >= 0 && valid) {
                v0 = act4(v0, ((const float4*)sAf)[f4i], ((const float4*)sCf)[f4i]);
                v1 = act4(v1, ((const float4*)sAf)[f4i + 1],
                          ((const float4*)sCf)[f4i + 1]);
            }
            float f[8] = {v0.x, v0.y, v0.z, v0.w, v1.x, v1.y, v1.z, v1.w};
            uint4 hi, lo;
            uint32_t* hp = (uint32_t*)&hi;
            uint32_t* lp = (uint32_t*)&lo;
#pragma unroll
            for (int j = 0; j < 4; j++) {
                float x0 = f[j * 2], x1 = f[j * 2 + 1];
                __nv_bfloat16 h0 = __float2bfloat16(x0);
                __nv_bfloat16 h1 = __float2bfloat16(x1);
                hp[j] = (uint32_t)__bfloat16_as_ushort(h0) |
                        ((uint32_t)__bfloat16_as_ushort(h1) << 16);
                lp[j] = pack_bf16x2(x0 - __bfloat162float(h0),
                                    x1 - __bfloat162float(h1));
            }
            int off = r * 256 + (ch * 8 + c) * 16;
            int sw = off ^ ((r & 7) << 4);
            *(uint4*)(Ahi + sw) = hi;
            *(uint4*)(Alo + sw) = lo;
        }
    }
    __syncthreads();

    // ---- mma mainloop ----
    float acc[16][4];
#pragma unroll
    for (int n = 0; n < 16; n++)
#pragma unroll
        for (int j = 0; j < 4; j++) acc[n][j] = 0.f;

    int wrow = wid * 16;
    uint32_t aU = smem_u32(Ahi), bU = smem_u32(Bhi);
    int arow = wrow + (lane & 15);
    int akh = (lane >> 4) & 1;
    int aswb = ((arow & 7) << 4);
    int ntp = (lane >> 4) & 1;
    int bkh = (lane >> 3) & 1;
    int brow = lane & 7;
    int bswb = (brow << 4);

#pragma unroll
    for (int k = 0; k < 8; k++) {
        uint32_t afH[4], afL[4];
        {
            int aoff = arow * 256 + k * 32 + akh * 16;
            ldsm4(afH, aU + (uint32_t)(aoff ^ aswb));
            ldsm4(afL, aU + 32768u + (uint32_t)(aoff ^ aswb));
        }
        uint32_t bf[32];
#pragma unroll
        for (int p = 0; p < 8; p++) {
            int boff = ((2 * p + ntp) * 8 + brow) * 256 + k * 32 + bkh * 16;
            ldsm4(&bf[p * 4], bU + (uint32_t)(boff ^ bswb));
        }
#pragma unroll
        for (int p = 0; p < 8; p++) {           // hi * hi
            mma16816(acc[2 * p], afH, &bf[4 * p]);
            mma16816(acc[2 * p + 1], afH, &bf[4 * p + 2]);
        }
#pragma unroll
        for (int p = 0; p < 8; p++) {           // lo * hi
            mma16816(acc[2 * p], afL, &bf[4 * p]);
            mma16816(acc[2 * p + 1], afL, &bf[4 * p + 2]);
        }
#pragma unroll
        for (int p = 0; p < 8; p++) {
            int boff = ((2 * p + ntp) * 8 + brow) * 256 + k * 32 + bkh * 16;
            ldsm4(&bf[p * 4], bU + 32768u + (uint32_t)(boff ^ bswb));
        }
#pragma unroll
        for (int p = 0; p < 8; p++) {           // hi * lo
            mma16816(acc[2 * p], afH, &bf[4 * p]);
            mma16816(acc[2 * p + 1], afH, &bf[4 * p + 2]);
        }
    }

    // ---- epilogue: store Y + BN column stats ----
    int r0 = mBase + wrow + (lane >> 2);
    int r1 = r0 + 8;
#pragma unroll
    for (int n = 0; n < 16; n++) {
        int col = n * 8 + 2 * (lane & 3);
        if (r0 < NN)
            *(float2*)&Y[r0 * DD + col] = make_float2(acc[n][0], acc[n][1]);
        if (r1 < NN)
            *(float2*)&Y[r1 * DD + col] = make_float2(acc[n][2], acc[n][3]);
        float s0 = acc[n][0] + acc[n][2];
        float s1 = acc[n][1] + acc[n][3];
        float q0 = acc[n][0] * acc[n][0] + acc[n][2] * acc[n][2];
        float q1 = acc[n][1] * acc[n][1] + acc[n][3] * acc[n][3];
#pragma unroll
        for (int o = 4; o <= 16; o <<= 1) {
            s0 += __shfl_xor_sync(0xffffffffu, s0, o);
            s1 += __shfl_xor_sync(0xffffffffu, s1, o);
            q0 += __shfl_xor_sync(0xffffffffu, q0, o);
            q1 += __shfl_xor_sync(0xffffffffu, q1, o);
        }
        if (lane < 4) {
            int c2 = n * 8 + 2 * lane;
            atomicAdd(&cs[c2], s0);
            atomicAdd(&cs[c2 + 1], s1);
            atomicAdd(&cq[c2], q0);
            atomicAdd(&cq[c2 + 1], q1);
        }
    }
    __syncthreads();
    if (tid < DD) {
        atomicAdd(&g_ssum[statSlot][tid], cs[tid]);
        atomicAdd(&g_ssq[statSlot][tid], cq[tid]);
    }
}

// ---------------- readout ----------------
__global__ void k_nodeemb(float* __restrict__ out, const float* __restrict__ gm,
                          const float* __restrict__ bt) {
    __shared__ __align__(16) float sAf[DD], sCf[DD];
    int tid = threadIdx.x;
    bn_affine_block(5, gm, bt, sAf, sCf, tid);
    __syncthreads();
    int i = blockIdx.x * blockDim.x + tid;
    if (i >= NN * 32) return;
    int c4 = i & 31;
    float4 v = ((const float4*)g_h)[i];
    v = act4(v, ((const float4*)sAf)[c4], ((const float4*)sCf)[c4]);
    ((float4*)out)[i] = v;
}

// run-length graph sum + count (sorted batch)
__global__ void k_gsum(const float* __restrict__ emb, const void* bt) {
    int d = threadIdx.x;            // 128 threads = columns
    int beg = blockIdx.x * 256;
    int end = min(beg + 256, NN);
    if (beg >= NN) return;
    int is64 = g_flags[1];
    int cur = get_idx(bt, beg, is64);
    int runStart = beg;
    float acc = 0.f;
    for (int i = beg; i < end; i++) {
        int b = get_idx(bt, i, is64);
        if (b != cur) {
            atomicAdd(&g_gsum[cur * DD + d], acc);
            if (d == 0) atomicAdd(&g_gcnt[cur], i - runStart);
            acc = 0.f; cur = b; runStart = i;
        }
        acc += emb[i * DD + d];
    }
    atomicAdd(&g_gsum[cur * DD + d], acc);
    if (d == 0) atomicAdd(&g_gcnt[cur], end - runStart);
}

__global__ void k_gemb(float* __restrict__ out) {
    int g = blockIdx.x, d = threadIdx.x;
    float cnt = (float)g_gcnt[g];
    float v = g_gsum[g * DD + d] / fmaxf(cnt, 1.f);
    float s = v * v;
#pragma unroll
    for (int o = 16; o > 0; o >>= 1) s += __shfl_xor_sync(0xffffffffu, s, o);
    __shared__ float red[4];
    if ((d & 31) == 0) red[d >> 5] = s;
    __syncthreads();
    float tot = red[0] + red[1] + red[2] + red[3];
    float nrm = fmaxf(sqrtf(tot), 1e-12f);
    out[NN * DD + g * DD + d] = v / nrm;
}

// ---------------- launch ----------------
extern "C" void kernel_launch(void* const* d_in, const int* in_sizes, int n_in,
                              void* d_out, int out_size) {
    const float* x  = (const float*)d_in[0];
    const void*  ei = d_in[1];
    const void*  bt = d_in[2];
    const float* W1 = (const float*)d_in[3];
    const float* g1 = (const float*)d_in[4];
    const float* b1 = (const float*)d_in[5];
    const float* W2 = (const float*)d_in[6];
    const float* g2 = (const float*)d_in[7];
    const float* b2 = (const float*)d_in[8];
    const float* eps = (const float*)d_in[9];
    float* out = (float*)d_out;
    (void)in_sizes; (void)n_in; (void)out_size;

    cudaFuncSetAttribute(k_gemmM, cudaFuncAttributeMaxDynamicSharedMemorySize,
                         GM_SMEM);

    k_setup<<<(NN + 255) / 256, 256>>>(ei, bt, W1, W2);
    k_count<<<(NE + 255) / 256, 256>>>(ei);
    k_scanA<<<SCAN_NB, 256>>>();
    k_scanB<<<1, 128>>>();
    k_scanC<<<SCAN_NB, 256>>>();
    k_fill<<<(NE + 255) / 256, 256>>>(ei);

    for (int l = 0; l < 3; l++) {
        int sPrev = 2 * l - 1;                    // BN2 of previous layer
        const float* gmP = (l == 0) ? g1 : (g2 + (l - 1) * DD);
        const float* btP = (l == 0) ? b1 : (b2 + (l - 1) * DD);
        k_agg<<<(NN * 32 + 255) / 256, 256>>>(x, l == 0 ? 1 : 0,
                                              l == 0 ? -1 : sPrev, gmP, btP,
                                              eps, l);
        k_gemmM<<<GM_GRID, 256, GM_SMEM>>>(0, 0, g1, b1, -1, 2 * l, 2 * l);
        k_gemmM<<<GM_GRID, 256, GM_SMEM>>>(1, 1, g1 + l * DD, b1 + l * DD,
                                           2 * l, 2 * l + 1, 2 * l + 1);
    }

    k_nodeemb<<<(NN * 32 + 255) / 256, 256>>>(out, g2 + 2 * DD, b2 + 2 * DD);
    k_gsum<<<(NN + 255) / 256, 128>>>(out, bt);
    k_gemb<<<NG, DD>>>(out);
}